// round 17
// baseline (speedup 1.0000x reference)
#include <cuda_runtime.h>
#include <math.h>

#define MM 8
#define NN 8192
#define KK 256
#define NUM_ITERS 6
#define FIX_ITER 1

#define LOG2E 1.44269504088896340736f
#define EPS_C 0.01f
#define GAMMA_C 0.005f

#define BPM 37            // blocks per shape m
#define NPB 222           // points per block
#define GRID (MM * BPM)   // 296 = 2 CTAs/SM on 148 SMs -> all resident

typedef unsigned long long u64;

static __device__ __forceinline__ float ex2f(float x) {
    float y; asm("ex2.approx.f32 %0, %1;" : "=f"(y) : "f"(x)); return y;
}
static __device__ __forceinline__ float rcpf(float x) {
    float y; asm("rcp.approx.f32 %0, %1;" : "=f"(y) : "f"(x)); return y;
}
static __device__ __forceinline__ float rsqf(float x) {
    float y; asm("rsqrt.approx.f32 %0, %1;" : "=f"(y) : "f"(x)); return y;
}
static __device__ __forceinline__ float lg2f(float x) {
    float y; asm("lg2.approx.f32 %0, %1;" : "=f"(y) : "f"(x)); return y;
}
static __device__ __forceinline__ u64 pk2(float lo, float hi) {
    u64 r; asm("mov.b64 %0, {%1, %2};" : "=l"(r)
               : "r"(__float_as_uint(lo)), "r"(__float_as_uint(hi)));
    return r;
}
static __device__ __forceinline__ void upk2(u64 v, float& lo, float& hi) {
    unsigned a, b; asm("mov.b64 {%0, %1}, %2;" : "=r"(a), "=r"(b) : "l"(v));
    lo = __uint_as_float(a); hi = __uint_as_float(b);
}
static __device__ __forceinline__ u64 fma2(u64 a, u64 b, u64 c) {
    u64 d; asm("fma.rn.f32x2 %0, %1, %2, %3;" : "=l"(d) : "l"(a), "l"(b), "l"(c)); return d;
}
static __device__ __forceinline__ u64 mul2(u64 a, u64 b) {
    u64 d; asm("mul.rn.f32x2 %0, %1, %2;" : "=l"(d) : "l"(a), "l"(b)); return d;
}
static __device__ __forceinline__ u64 add2(u64 a, u64 b) {
    u64 d; asm("add.rn.f32x2 %0, %1, %2;" : "=l"(d) : "l"(a), "l"(b)); return d;
}

// ------------- persistent device state (no allocations allowed) -------------
// 3 rotating moment buffers, point-major padded records:
// gMom[buf][m][k][8] = {L, WTx, WTy, WTz, ST, pad, pad, pad}  (32B aligned)
__device__ float gMom[3][MM][KK][8];
__device__ float gT0f[24];
__device__ float gBeta;

__device__ unsigned g_arrive = 0;
__device__ volatile unsigned g_phase = 0;

static __device__ __forceinline__ void grid_barrier() {
    __syncthreads();
    if (threadIdx.x == 0) {
        unsigned p = g_phase;
        __threadfence();
        unsigned rank = atomicAdd(&g_arrive, 1u);
        if (rank == GRID - 1) {
            g_arrive = 0;
            __threadfence();
            g_phase = p + 1;
        } else {
            while (g_phase == p) __nanosleep(32);
        }
        __threadfence();
    }
    __syncthreads();
}

#define ZTOT (MM * KK * 8)   // floats per moment buffer = 16384

// ------------------------------ fused kernel ---------------------------------
__global__ void __launch_bounds__(256, 2)
fused_kernel(const float* __restrict__ Vs,
             const float* __restrict__ X0,
             const float* __restrict__ Q0,
             float* __restrict__ out) {
    int bid = blockIdx.x, tid = threadIdx.x;
    int lane = tid & 31, warp = tid >> 5;

    // ----- shared: staged transformed points, interleaved 32B records --------
    // sPt[i*8 + {0..7}] = {Tx,Tx,Ty,Ty,Tz,Tz,hT,hT}
    __shared__ __align__(16) float sPt[NPB * 8];
    __shared__ float s5[5][KK];
    // per-block replicated model state
    __shared__ float sC0[KK], sC1[KK], sDx[KK], sDy[KK], sDz[KK];
    __shared__ float sQ[KK], sX[3 * KK];
    __shared__ float sRm[72], sTm[24];          // current R (row-major), t per shape
    __shared__ float sRold[72], sTold[24];      // snapshot for solve
    __shared__ float sM[72], sTn[24];           // M = Rnew*Rold^T, new t
    __shared__ float smz[8], smx[24], smw[24], smp[72];
    __shared__ float sred[8];
    __shared__ float sBeta;

    // ------------------------------ init ------------------------------------
    // zero all 3 moment buffers (distributed across grid)
    for (int i = tid + bid * 256; i < 3 * ZTOT; i += GRID * 256)
        ((float*)gMom)[i] = 0.f;

    if (bid < 24) {
        int m = bid / 3, d = bid % 3;
        const float* src = Vs + (m * 3 + d) * NN;
        float s = 0.f;
        for (int n = tid; n < NN; n += 256) s += __ldg(src + n);
        #pragma unroll
        for (int o = 16; o; o >>= 1) s += __shfl_xor_sync(0xffffffffu, s, o);
        if (lane == 0) sred[warp] = s;
        __syncthreads();
        if (tid == 0) {
            float t = 0.f;
            for (int w = 0; w < 8; w++) t += sred[w];
            gT0f[bid] = -t / (float)NN;
        }
    } else if (bid == 24) {
        float q = __ldg(Q0 + tid);
        float s = q;
        #pragma unroll
        for (int o = 16; o; o >>= 1) s += __shfl_xor_sync(0xffffffffu, s, o);
        if (lane == 0) sred[warp] = s;
        __syncthreads();
        if (tid == 0) {
            float t = 0.f;
            for (int w = 0; w < 8; w++) t += sred[w];
            float mq = t / (float)KK;
            gBeta = GAMMA_C * mq * sqrtf(mq);
        }
    }
    grid_barrier();

    // ------------------------- per-block state setup --------------------------
    {
        int k = tid;
        float q = __ldg(Q0 + k);
        float x0 = __ldg(X0 + 3 * k), x1 = __ldg(X0 + 3 * k + 1), x2 = __ldg(X0 + 3 * k + 2);
        sQ[k] = q;
        sX[3 * k] = x0; sX[3 * k + 1] = x1; sX[3 * k + 2] = x2;
        float xs = x0 * x0 + x1 * x1 + x2 * x2;
        sC1[k] = -0.5f * q * LOG2E;
        sC0[k] = 1.5f * log2f(q) - 0.5f * q * xs * LOG2E;
        sDx[k] = q * LOG2E * x0;
        sDy[k] = q * LOG2E * x1;
        sDz[k] = q * LOG2E * x2;
    }
    if (tid < 72) sRm[tid] = ((tid % 9) % 4 == 0) ? 1.f : 0.f;
    if (tid < 24) sTm[tid] = __ldcg(&gT0f[tid]);
    if (tid == 0) sBeta = __ldcg(&gBeta);

    int m   = bid / BPM;
    int blk = bid % BPM;
    int n0 = blk * NPB;
    int count = min(NPB, NN - n0);
    const float* V0 = Vs + m * 3 * NN + n0;

    unsigned sPtBase = (unsigned)__cvta_generic_to_shared(sPt);

    // zero-slice ownership for the rotating buffers
    int zper = (ZTOT + GRID - 1) / GRID;   // 56
    int zb = bid * zper;

    for (int it = 0; it < NUM_ITERS; it++) {
        int pc = it % 3;             // current buffer
        int pn = (it + 1) % 3;       // buffer to zero for next iter
        __syncthreads();             // state (sRm/sTm/consts) visible

        // ---- stage: transform points into T-space (interleaved 32B records) --
        if (tid < count) {
            float r0 = sRm[m * 9 + 0], r1 = sRm[m * 9 + 1], r2 = sRm[m * 9 + 2];
            float r3 = sRm[m * 9 + 3], r4 = sRm[m * 9 + 4], r5 = sRm[m * 9 + 5];
            float r6 = sRm[m * 9 + 6], r7 = sRm[m * 9 + 7], r8 = sRm[m * 9 + 8];
            float t0 = sTm[m * 3 + 0], t1 = sTm[m * 3 + 1], t2 = sTm[m * 3 + 2];
            float vx = __ldg(V0 + tid), vy = __ldg(V0 + NN + tid), vz = __ldg(V0 + 2 * NN + tid);
            float Tx = fmaf(r0, vx, fmaf(r1, vy, fmaf(r2, vz, t0)));
            float Ty = fmaf(r3, vx, fmaf(r4, vy, fmaf(r5, vz, t1)));
            float Tz = fmaf(r6, vx, fmaf(r7, vy, fmaf(r8, vz, t2)));
            float hT = fmaf(Tx, Tx, fmaf(Ty, Ty, Tz * Tz));
            float4* p4 = (float4*)&sPt[tid * 8];
            p4[0] = make_float4(Tx, Tx, Ty, Ty);
            p4[1] = make_float4(Tz, Tz, hT, hT);
        }
        // zero this block's slice of NEXT buffer (safe: last read at solve_{it-2},
        // complete before B_{it-1}; next writes happen after B_it)
        {
            float* zn = (float*)gMom[pn];
            for (int j = tid; j < zper; j += 256)
                if (zb + j < ZTOT) zn[zb + j] = 0.f;
        }
        for (int i = tid; i < 5 * KK; i += 256) ((float*)s5)[i] = 0.f;

        // fixed-point scale prep: warp-max of current Q
        {
            float qk = sQ[tid];
            #pragma unroll
            for (int o = 16; o; o >>= 1)
                qk = fmaxf(qk, __shfl_xor_sync(0xffffffffu, qk, o));
            if (lane == 0) sred[warp] = qk;
        }

        // packed per-lane cluster constants: pair jj -> clusters (lane+64jj, +32)
        u64 C0p[4], C1p[4], DxP[4], DyP[4], DzP[4];
        #pragma unroll
        for (int jj = 0; jj < 4; jj++) {
            int ka = lane + 64 * jj, kb = ka + 32;
            C0p[jj] = pk2(sC0[ka], sC0[kb]);
            C1p[jj] = pk2(sC1[ka], sC1[kb]);
            DxP[jj] = pk2(sDx[ka], sDx[kb]);
            DyP[jj] = pk2(sDy[ka], sDy[kb]);
            DzP[jj] = pk2(sDz[ka], sDz[kb]);
        }
        float beta = sBeta;

        u64 aLp[4], aWxp[4], aWyp[4], aWzp[4], aSp[4];
        #pragma unroll
        for (int jj = 0; jj < 4; jj++) {
            aLp[jj] = 0ull; aWxp[jj] = 0ull; aWyp[jj] = 0ull; aWzp[jj] = 0ull; aSp[jj] = 0ull;
        }
        __syncthreads();

        // deterministic fixed-point scale (identical in every block/thread):
        // per-lane partial bound = 8*maxQ^1.5; scaled to <= 2^21 (1 bit margin)
        float scalef, invscalef;
        {
            float qmax = sred[0];
            #pragma unroll
            for (int w = 1; w < 8; w++) qmax = fmaxf(qmax, sred[w]);
            float mq15 = qmax * sqrtf(qmax);
            float l8 = ceilf(lg2f(8.f * mq15));
            scalef    = ex2f(21.f - l8);
            invscalef = ex2f(l8 - 21.f);
        }

        int beg = warp * 28;
        int end = min(beg + 28, count);
        unsigned pbase = sPtBase + (unsigned)(beg * 32);

        #pragma unroll 2
        for (int i = beg; i < end; i++) {
            u64 Txp, Typ, Tzp, hTp;
            asm("ld.shared.v2.b64 {%0, %1}, [%2];" : "=l"(Txp), "=l"(Typ) : "r"(pbase));
            asm("ld.shared.v2.b64 {%0, %1}, [%2];" : "=l"(Tzp), "=l"(hTp) : "r"(pbase + 16));
            pbase += 32;

            u64 app[4];
            #pragma unroll
            for (int jj = 0; jj < 4; jj++) {
                u64 arg = fma2(C1p[jj], hTp, C0p[jj]);
                arg = fma2(DxP[jj], Txp, arg);
                arg = fma2(DyP[jj], Typ, arg);
                arg = fma2(DzP[jj], Tzp, arg);
                float lo, hi; upk2(arg, lo, hi);
                app[jj] = pk2(ex2f(lo), ex2f(hi));
            }
            // packed add-tree, magic-number float->fixed, HW integer reduction.
            // Mantissa field of (v + 2^23 + 2^22) is 0x400000 + v; mask the LOW
            // 22 BITS (v < 2^22 guaranteed by the scale bound) to recover v.
            u64 s01 = add2(app[0], app[1]);
            u64 s23 = add2(app[2], app[3]);
            u64 stot = add2(s01, s23);
            float slo, shi; upk2(stot, slo, shi);
            float ymag = fmaf(slo + shi, scalef, 12582912.0f);   // 2^23 + 2^22
            unsigned pi = __float_as_uint(ymag) & 0x003FFFFFu;   // 22-bit mask
            unsigned si = __reduce_add_sync(0xffffffffu, pi);
            float inv = rcpf(fmaf(__uint2float_rn(si), invscalef, beta));
            u64 invp = pk2(inv, inv);

            #pragma unroll
            for (int jj = 0; jj < 4; jj++) {
                u64 a = mul2(app[jj], invp);
                aLp[jj]  = add2(aLp[jj], a);
                aWxp[jj] = fma2(Txp, a, aWxp[jj]);
                aWyp[jj] = fma2(Typ, a, aWyp[jj]);
                aWzp[jj] = fma2(Tzp, a, aWzp[jj]);
                aSp[jj]  = fma2(hTp, a, aSp[jj]);
            }
        }

        // ---- block-level shared reduction, then global atomics ----
        #pragma unroll
        for (int jj = 0; jj < 4; jj++) {
            int ka = lane + 64 * jj, kb = ka + 32;
            float lo, hi;
            upk2(aLp[jj],  lo, hi); atomicAdd(&s5[0][ka], lo); atomicAdd(&s5[0][kb], hi);
            upk2(aWxp[jj], lo, hi); atomicAdd(&s5[1][ka], lo); atomicAdd(&s5[1][kb], hi);
            upk2(aWyp[jj], lo, hi); atomicAdd(&s5[2][ka], lo); atomicAdd(&s5[2][kb], hi);
            upk2(aWzp[jj], lo, hi); atomicAdd(&s5[3][ka], lo); atomicAdd(&s5[3][kb], hi);
            upk2(aSp[jj],  lo, hi); atomicAdd(&s5[4][ka], lo); atomicAdd(&s5[4][kb], hi);
        }
        __syncthreads();
        {
            float* gk = &gMom[pc][m][tid][0];
            atomicAdd(gk + 0, s5[0][tid]);
            atomicAdd(gk + 1, s5[1][tid]);
            atomicAdd(gk + 2, s5[2][tid]);
            atomicAdd(gk + 3, s5[3][tid]);
            atomicAdd(gk + 4, s5[4][tid]);
        }

        grid_barrier();

        // --------------------- solve (redundant, every block) -----------------
        // snapshot old R, t
        if (tid < 72) sRold[tid] = sRm[tid];
        if (tid < 24) sTold[tid] = sTm[tid];
        __syncthreads();

        // phase 1: warp == shape moment reduction (raw-space recovery)
        {
            int mm = warp;
            float Ro0 = sRold[mm*9+0], Ro1 = sRold[mm*9+1], Ro2 = sRold[mm*9+2];
            float Ro3 = sRold[mm*9+3], Ro4 = sRold[mm*9+4], Ro5 = sRold[mm*9+5];
            float Ro6 = sRold[mm*9+6], Ro7 = sRold[mm*9+7], Ro8 = sRold[mm*9+8];
            float tox = sTold[mm*3+0], toy = sTold[mm*3+1], toz = sTold[mm*3+2];
            float p[16];
            #pragma unroll
            for (int q = 0; q < 16; q++) p[q] = 0.f;
            #pragma unroll
            for (int j = 0; j < 8; j++) {
                int kk = lane + 32 * j;
                float4 v0 = __ldcg((const float4*)&gMom[pc][mm][kk][0]);
                float L = v0.x, WTx = v0.y, WTy = v0.z, WTz = v0.w;
                float Q   = sQ[kk];
                float x0  = sX[3*kk], x1 = sX[3*kk+1], x2 = sX[3*kk+2];
                float WX = WTx - tox * L, WY = WTy - toy * L, WZ = WTz - toz * L;
                float wrx = Ro0 * WX + Ro3 * WY + Ro6 * WZ;   // Rold^T W
                float wry = Ro1 * WX + Ro4 * WY + Ro7 * WZ;
                float wrz = Ro2 * WX + Ro5 * WY + Ro8 * WZ;
                float b = L * Q;
                float wqx = wrx * Q, wqy = wry * Q, wqz = wrz * Q;
                p[0] += b;
                p[1] = fmaf(b, x0, p[1]);  p[2] = fmaf(b, x1, p[2]);  p[3] = fmaf(b, x2, p[3]);
                p[4] += wqx; p[5] += wqy; p[6] += wqz;
                p[7]  = fmaf(wqx, x0, p[7]);  p[8]  = fmaf(wqy, x0, p[8]);  p[9]  = fmaf(wqz, x0, p[9]);
                p[10] = fmaf(wqx, x1, p[10]); p[11] = fmaf(wqy, x1, p[11]); p[12] = fmaf(wqz, x1, p[12]);
                p[13] = fmaf(wqx, x2, p[13]); p[14] = fmaf(wqy, x2, p[14]); p[15] = fmaf(wqz, x2, p[15]);
            }
            #pragma unroll
            for (int q = 0; q < 16; q++) {
                float v = p[q];
                #pragma unroll
                for (int o = 16; o; o >>= 1) v += __shfl_xor_sync(0xffffffffu, v, o);
                p[q] = v;
            }
            if (lane == 0) {
                smz[mm] = p[0];
                smx[mm*3+0] = p[1]; smx[mm*3+1] = p[2]; smx[mm*3+2] = p[3];
                smw[mm*3+0] = p[4]; smw[mm*3+1] = p[5]; smw[mm*3+2] = p[6];
                #pragma unroll
                for (int q = 0; q < 9; q++) smp[mm*9+q] = p[7+q];
            }
        }
        __syncthreads();

        // 3x3 SVD per shape (8 threads, fp32 Jacobi; IEEE sqrt for inf-safety)
        if (tid < MM) {
            int mm = tid;
            float z = smz[mm];
            float invz = rcpf(z);
            float mX[3], mW[3];
            for (int d = 0; d < 3; d++) { mX[d] = smx[mm*3+d]; mW[d] = smw[mm*3+d]; }
            float P[3][3];
            for (int e = 0; e < 3; e++)
                for (int d = 0; d < 3; d++)
                    P[e][d] = smp[mm*9 + e*3 + d] - mX[e] * mW[d] * invz;

            float A[3][3], V[3][3];
            for (int i = 0; i < 3; i++)
                for (int j = 0; j < 3; j++) {
                    A[i][j] = P[0][i]*P[0][j] + P[1][i]*P[1][j] + P[2][i]*P[2][j];
                    V[i][j] = (i == j) ? 1.f : 0.f;
                }
            #pragma unroll 1
            for (int sw = 0; sw < 6; sw++) {
                #pragma unroll
                for (int pi2 = 0; pi2 < 3; pi2++) {
                    int p = (pi2 == 2) ? 1 : 0;
                    int q = (pi2 == 0) ? 1 : 2;
                    float apq = A[p][q];
                    if (fabsf(apq) > 1e-20f) {
                        float theta = (A[q][q] - A[p][p]) * 0.5f * rcpf(apq);
                        // sqrtf is inf-safe: theta=inf -> sqrt(inf)=inf -> rcpf(inf)=0 -> tt=0
                        float tt = ((theta >= 0.f) ? 1.f : -1.f)
                                 * rcpf(fabsf(theta) + sqrtf(fmaf(theta, theta, 1.f)));
                        float c = rsqf(fmaf(tt, tt, 1.f));
                        float s = tt * c;
                        int r = 3 - p - q;
                        float arp = A[r][p], arq = A[r][q];
                        A[p][p] -= tt * apq;
                        A[q][q] += tt * apq;
                        A[p][q] = 0.f; A[q][p] = 0.f;
                        float nrp = c * arp - s * arq, nrq = s * arp + c * arq;
                        A[r][p] = nrp; A[p][r] = nrp; A[r][q] = nrq; A[q][r] = nrq;
                        #pragma unroll
                        for (int rr = 0; rr < 3; rr++) {
                            float vp = V[rr][p], vq = V[rr][q];
                            V[rr][p] = c * vp - s * vq;
                            V[rr][q] = s * vp + c * vq;
                        }
                    }
                }
            }
            float ev[3] = { A[0][0], A[1][1], A[2][2] };
            #pragma unroll
            for (int pass = 0; pass < 3; pass++) {
                int i = (pass == 1) ? 1 : 0, j = i + 1;
                if (ev[j] > ev[i]) {
                    float te = ev[i]; ev[i] = ev[j]; ev[j] = te;
                    for (int r = 0; r < 3; r++) { float tv = V[r][i]; V[r][i] = V[r][j]; V[r][j] = tv; }
                }
            }
            float u[3][3];
            #pragma unroll
            for (int i = 0; i < 2; i++) {
                float sg2 = fmaxf(ev[i], 0.f);
                float inv = (sg2 > 1e-30f) ? rsqf(sg2) : 0.f;
                for (int e = 0; e < 3; e++)
                    u[i][e] = (P[e][0]*V[0][i] + P[e][1]*V[1][i] + P[e][2]*V[2][i]) * inv;
            }
            {
                float n0 = u[0][0]*u[0][0] + u[0][1]*u[0][1] + u[0][2]*u[0][2];
                float in0 = (n0 > 1e-30f) ? rsqf(n0) : 0.f;
                for (int e = 0; e < 3; e++) u[0][e] *= in0;
                float d01 = u[0][0]*u[1][0] + u[0][1]*u[1][1] + u[0][2]*u[1][2];
                for (int e = 0; e < 3; e++) u[1][e] -= d01 * u[0][e];
                float n1 = u[1][0]*u[1][0] + u[1][1]*u[1][1] + u[1][2]*u[1][2];
                float in1 = (n1 > 1e-30f) ? rsqf(n1) : 0.f;
                for (int e = 0; e < 3; e++) u[1][e] *= in1;
            }
            u[2][0] = u[0][1]*u[1][2] - u[0][2]*u[1][1];
            u[2][1] = u[0][2]*u[1][0] - u[0][0]*u[1][2];
            u[2][2] = u[0][0]*u[1][1] - u[0][1]*u[1][0];
            float detV = V[0][0]*(V[1][1]*V[2][2] - V[1][2]*V[2][1])
                       - V[0][1]*(V[1][0]*V[2][2] - V[1][2]*V[2][0])
                       + V[0][2]*(V[1][0]*V[2][1] - V[1][1]*V[2][0]);
            float dlt = (detV >= 0.f) ? 1.f : -1.f;

            float R[3][3];
            for (int a = 0; a < 3; a++)
                for (int b = 0; b < 3; b++)
                    R[a][b] = u[0][a]*V[b][0] + u[1][a]*V[b][1] + dlt*u[2][a]*V[b][2];
            float t[3];
            for (int a = 0; a < 3; a++)
                t[a] = (mX[a] - (R[a][0]*mW[0] + R[a][1]*mW[1] + R[a][2]*mW[2])) * invz;

            for (int a = 0; a < 3; a++) {
                for (int b = 0; b < 3; b++) {
                    sRm[mm*9 + a*3 + b] = R[a][b];
                    // M = Rnew * Rold^T
                    sM[mm*9 + a*3 + b] = R[a][0]*sRold[mm*9 + b*3 + 0]
                                       + R[a][1]*sRold[mm*9 + b*3 + 1]
                                       + R[a][2]*sRold[mm*9 + b*3 + 2];
                }
                sTm[mm*3 + a] = t[a];
                sTn[mm*3 + a] = t[a];
            }
        }
        __syncthreads();

        // epilogue: per-cluster X/Q update (thread == cluster), all in shared
        {
            int k = tid;
            float Xk0 = sX[3*k], Xk1 = sX[3*k+1], Xk2 = sX[3*k+2];
            float den = 0.f, Nx = 0.f, Ny = 0.f, Nz = 0.f, sA = 0.f;
            #pragma unroll
            for (int mm = 0; mm < MM; mm++) {
                const float* gk = &gMom[pc][mm][k][0];
                float4 v0 = __ldcg((const float4*)gk);
                float L = v0.x, WTx = v0.y, WTy = v0.z, WTz = v0.w;
                float ST = __ldcg(gk + 4);
                float tox = sTold[mm*3+0], toy = sTold[mm*3+1], toz = sTold[mm*3+2];
                float tnx = sTn[mm*3+0],  tny = sTn[mm*3+1],  tnz = sTn[mm*3+2];
                float WX = WTx - tox * L, WY = WTy - toy * L, WZ = WTz - toz * L;
                float RWx = sM[mm*9+0]*WX + sM[mm*9+1]*WY + sM[mm*9+2]*WZ;
                float RWy = sM[mm*9+3]*WX + sM[mm*9+4]*WY + sM[mm*9+5]*WZ;
                float RWz = sM[mm*9+6]*WX + sM[mm*9+7]*WY + sM[mm*9+8]*WZ;
                float S2 = ST - 2.f*(tox*WTx + toy*WTy + toz*WTz)
                         + (tox*tox + toy*toy + toz*toz) * L;
                den += L;
                Nx += RWx + tnx * L;
                Ny += RWy + tny * L;
                Nz += RWz + tnz * L;
                sA += S2 + 2.f*(tnx*RWx + tny*RWy + tnz*RWz)
                    + (tnx*tnx + tny*tny + tnz*tnz) * L;
            }

            float Xn0, Xn1, Xn2;
            if (it > FIX_ITER) {
                float id = rcpf(den);
                Xn0 = Nx * id; Xn1 = Ny * id; Xn2 = Nz * id;
            } else {
                Xn0 = Xk0; Xn1 = Xk1; Xn2 = Xk2;
            }
            float xn2 = Xn0*Xn0 + Xn1*Xn1 + Xn2*Xn2;
            float wn = sA + xn2 * den - 2.f*(Xn0*Nx + Xn1*Ny + Xn2*Nz);
            float Qn = 3.f * den * rcpf(wn + 3.f * den * EPS_C);

            sX[3*k] = Xn0; sX[3*k+1] = Xn1; sX[3*k+2] = Xn2;
            sQ[k] = Qn;
            sC1[k] = -0.5f * Qn * LOG2E;
            sC0[k] = 1.5f * lg2f(Qn) - 0.5f * Qn * xn2 * LOG2E;
            sDx[k] = Qn * LOG2E * Xn0;
            sDy[k] = Qn * LOG2E * Xn1;
            sDz[k] = Qn * LOG2E * Xn2;
        }
        // top-of-loop __syncthreads() separates epilogue writes from next stage
    }

    // ------------------------------ finalize ---------------------------------
    __syncthreads();
    {
        const int TOT = MM * 3 * NN;                  // 196608
        int per = (TOT + GRID - 1) / GRID;            // 665
        int s = bid * per, e = min(s + per, TOT);
        for (int idx = s + tid; idx < e; idx += 256) {
            int n = idx % NN;
            int md = idx / NN;
            int mq = md / 3;
            const float* Vm = Vs + mq * 3 * NN;
            float vx = __ldg(Vm + n), vy = __ldg(Vm + NN + n), vz = __ldg(Vm + 2 * NN + n);
            out[idx] = fmaf(sRm[3*md], vx, fmaf(sRm[3*md+1], vy, fmaf(sRm[3*md+2], vz, sTm[md])));
        }
        if (bid == 0) {
            if (tid < 72) out[196608 + tid] = sRm[tid];
            if (tid < 24) out[196680 + tid] = sTm[tid];
            for (int i = tid; i < 768; i += 256)
                out[196704 + i] = sX[i];
        }
    }
}

// ------------------------------ launch --------------------------------------
extern "C" void kernel_launch(void* const* d_in, const int* in_sizes, int n_in,
                              void* d_out, int out_size) {
    const float* Vs = (const float*)d_in[0];
    const float* X0 = (const float*)d_in[1];
    const float* Q0 = (const float*)d_in[2];
    float* out = (float*)d_out;

    fused_kernel<<<GRID, 256>>>(Vs, X0, Q0, out);
}